// round 15
// baseline (speedup 1.0000x reference)
#include <cuda_runtime.h>
#include <cuda_bf16.h>
#include <cstdint>

#define B_ 32
#define S_ 2048
#define D_ 1024
#define E_ 64
#define K_ 8
#define T_ 128       // N_TAGS
#define KSPLIT 8
#define KCHUNK 128   // K per split
#define KS 32        // k sub-chunk (bf16 elems) staged in smem
#define RSTR 40      // bf16 elems per smem row (80B: conflict-free, 16B aligned)
#define AH_OFF 0
#define AL_OFF (64 * RSTR)          // 2560
#define BH_OFF (2 * 64 * RSTR)      // 5120
#define BL_OFF (BH_OFF + 128 * RSTR) // 10240
#define STG_ELE (BL_OFF + 128 * RSTR) // 15360 bf16 = 30720 B per stage

// Scratch (allocation-free rule: __device__ globals)
__device__ __nv_bfloat16 g_eh[B_ * E_ * D_];     // 4 MB pooled, bf16-hi
__device__ __nv_bfloat16 g_el[B_ * E_ * D_];     // 4 MB pooled, bf16-lo
__device__ __nv_bfloat16 g_wh[T_ * D_];          // fc_w bf16-hi [T][D]
__device__ __nv_bfloat16 g_wl[T_ * D_];          // fc_w bf16-lo [T][D]
__device__ float g_part[KSPLIT * B_ * E_ * T_];  // 8 MB k-split partials
__device__ unsigned int g_sem[B_ * E_ / 64];     // per-m-tile arrival counters
                                                 // (zero-init; self-reset)

// ---- helpers ----------------------------------------------------------------
__device__ __forceinline__ uint32_t pack_hi_lo(float a, float b,
                                               float& ra, float& rb) {
    __nv_bfloat16 ha = __float2bfloat16_rn(a);
    __nv_bfloat16 hb = __float2bfloat16_rn(b);
    ra = a - __bfloat162float(ha);
    rb = b - __bfloat162float(hb);
    uint16_t ua = *(uint16_t*)&ha, ub = *(uint16_t*)&hb;
    return (uint32_t)ua | ((uint32_t)ub << 16);
}
__device__ __forceinline__ uint32_t pack_bf2(float a, float b) {
    __nv_bfloat16 ha = __float2bfloat16_rn(a);
    __nv_bfloat16 hb = __float2bfloat16_rn(b);
    uint16_t ua = *(uint16_t*)&ha, ub = *(uint16_t*)&hb;
    return (uint32_t)ua | ((uint32_t)ub << 16);
}

__device__ __forceinline__ void ldsm4(uint32_t* r, uint32_t addr) {
    asm volatile("ldmatrix.sync.aligned.m8n8.x4.shared.b16 {%0,%1,%2,%3}, [%4];"
                 : "=r"(r[0]), "=r"(r[1]), "=r"(r[2]), "=r"(r[3]) : "r"(addr));
}
__device__ __forceinline__ void mma16(float* d, const uint32_t* a,
                                      uint32_t b0, uint32_t b1) {
    asm volatile(
        "mma.sync.aligned.m16n8k16.row.col.f32.bf16.bf16.f32 "
        "{%0,%1,%2,%3}, {%4,%5,%6,%7}, {%8,%9}, {%0,%1,%2,%3};"
        : "+f"(d[0]), "+f"(d[1]), "+f"(d[2]), "+f"(d[3])
        : "r"(a[0]), "r"(a[1]), "r"(a[2]), "r"(a[3]), "r"(b0), "r"(b1));
}
__device__ __forceinline__ void cp16(uint32_t dst, const void* src) {
    asm volatile("cp.async.cg.shared.global [%0], [%1], 16;"
                 :: "r"(dst), "l"(src) : "memory");
}

// ---------------------------------------------------------------------------
// Kernel P: gather + masked mean pool -> bf16 hi/lo split outputs (R12-proven).
// ---------------------------------------------------------------------------
__global__ __launch_bounds__(256) void pool_kernel(
    const float* __restrict__ hs,      // [B,S,D]
    const int*   __restrict__ idx,     // [B,E,K]
    const int*   __restrict__ counts,  // [B,E]
    const int*   __restrict__ nent,    // [B]
    const float* __restrict__ W)       // fc_w [T,D]
{
    int be = blockIdx.x;           // 0..2047
    int b  = be >> 6;
    int e  = be & 63;
    int t  = threadIdx.x;

    int cnt    = counts[be];
    int ne     = nent[b];
    int4 ia    = *(const int4*)(idx + be * K_);
    int4 ib    = *(const int4*)(idx + be * K_ + 4);
    bool active = (e < ne);

    int r[8] = {ia.x, ia.y, ia.z, ia.w, ib.x, ib.y, ib.z, ib.w};
    #pragma unroll
    for (int k = 1; k < K_; ++k)
        r[k] = (k < cnt) ? r[k] : r[0];   // clamp -> dup loads hit L1

    float4 acc = make_float4(0.f, 0.f, 0.f, 0.f);
    if (active) {
        const float* base = hs + (size_t)b * (S_ * D_) + t * 4;
        float4 v[8];
        #pragma unroll
        for (int k = 0; k < K_; ++k)      // 8 unconditional batched LDG.128
            v[k] = *(const float4*)(base + (size_t)r[k] * D_);
        float inv = 1.0f / (float)cnt;
        #pragma unroll
        for (int k = 0; k < K_; ++k) {
            float w = (k < cnt) ? inv : 0.f;
            acc.x = fmaf(v[k].x, w, acc.x);
            acc.y = fmaf(v[k].y, w, acc.y);
            acc.z = fmaf(v[k].z, w, acc.z);
            acc.w = fmaf(v[k].w, w, acc.w);
        }
    }

    float rx, ry, rz, rw;
    uint2 hv, lv;
    hv.x = pack_hi_lo(acc.x, acc.y, rx, ry);
    hv.y = pack_hi_lo(acc.z, acc.w, rz, rw);
    lv.x = pack_bf2(rx, ry);
    lv.y = pack_bf2(rz, rw);
    *(uint2*)(g_eh + (size_t)be * D_ + t * 4) = hv;
    *(uint2*)(g_el + (size_t)be * D_ + t * 4) = lv;

    // fc_w hi/lo split: 512 blocks x 256 elements
    if (blockIdx.x < (T_ * D_) / 256) {
        int i = blockIdx.x * 256 + t;
        float w = W[i];
        __nv_bfloat16 wh = __float2bfloat16_rn(w);
        g_wh[i] = wh;
        g_wl[i] = __float2bfloat16_rn(w - __bfloat162float(wh));
    }
}

// ---------------------------------------------------------------------------
// Kernel B: bf16x3 split-K GEMM (R12-proven mainloop) + inline semaphore
// reduction: the last-arriving CTA of each m-tile sums the 8 partials, adds
// bias, writes out, and self-resets the counter.
// grid = (32 m-tiles, 8 k-splits) = 256 CTAs (2/SM), 256 threads (8 warps).
// ---------------------------------------------------------------------------
__global__ __launch_bounds__(256, 2) void mma_gemm(
    const float* __restrict__ bias,    // [T]
    float*       __restrict__ out)     // [B*E, T]
{
    extern __shared__ __nv_bfloat16 sm[];
    __shared__ unsigned int s_last;
    uint32_t smb;
    asm("{ .reg .u64 t; cvta.to.shared.u64 t, %1; cvt.u32.u64 %0, t; }"
        : "=r"(smb) : "l"(sm));

    int tid  = threadIdx.x;
    int lane = tid & 31;
    int warp = tid >> 5;
    int mi = warp >> 2;            // 0..1  -> m-sub (32 rows)
    int ni = warp & 3;             // 0..3  -> n-sub (32 cols)
    int mblk  = blockIdx.x;
    int mrow0 = mblk * 64;
    int split = blockIdx.y;
    int kbase = split * KCHUNK;

    // ldmatrix per-lane offsets (bf16 elems)
    int tile = lane >> 3;
    int tr   = lane & 7;
    int aoff[2], boff[2];
    #pragma unroll
    for (int f = 0; f < 2; ++f)
        aoff[f] = (mi * 32 + f * 16 + (tile & 1) * 8 + tr) * RSTR + (tile >> 1) * 8;
    #pragma unroll
    for (int n2 = 0; n2 < 2; ++n2)
        boff[n2] = (ni * 32 + n2 * 16 + (tile >> 1) * 8 + tr) * RSTR + (tile & 1) * 8;

    float acc[2][4][4];
    #pragma unroll
    for (int f = 0; f < 2; ++f)
        #pragma unroll
        for (int n = 0; n < 4; ++n)
            #pragma unroll
            for (int p = 0; p < 4; ++p) acc[f][n][p] = 0.f;

    auto issue = [&](int stg, int it) {
        int kc = kbase + it * KS;
        uint32_t sb = smb + (uint32_t)(stg * STG_ELE * 2);
        {
            int row = tid >> 2, q = tid & 3;
            size_t g = (size_t)(mrow0 + row) * D_ + kc + q * 8;
            cp16(sb + (uint32_t)((AH_OFF + row * RSTR + q * 8) * 2), g_eh + g);
            cp16(sb + (uint32_t)((AL_OFF + row * RSTR + q * 8) * 2), g_el + g);
        }
        #pragma unroll
        for (int j = 0; j < 2; ++j) {
            int i   = tid + j * 256;
            int row = i >> 2, q = i & 3;
            size_t g = (size_t)row * D_ + kc + q * 8;
            cp16(sb + (uint32_t)((BH_OFF + row * RSTR + q * 8) * 2), g_wh + g);
            cp16(sb + (uint32_t)((BL_OFF + row * RSTR + q * 8) * 2), g_wl + g);
        }
        asm volatile("cp.async.commit_group;" ::: "memory");
    };

    issue(0, 0);

    #pragma unroll 1
    for (int it = 0; it < KCHUNK / KS; ++it) {
        int s = it & 1;
        asm volatile("cp.async.wait_group 0;" ::: "memory");
        __syncthreads();
        if (it + 1 < KCHUNK / KS) issue((it + 1) & 1, it + 1);

        uint32_t sb = smb + (uint32_t)(s * STG_ELE * 2);

        #pragma unroll
        for (int ks = 0; ks < KS / 16; ++ks) {
            uint32_t aH[2][4], aL[2][4];
            #pragma unroll
            for (int f = 0; f < 2; ++f) {
                ldsm4(aH[f], sb + (uint32_t)((AH_OFF + aoff[f] + ks * 16) * 2));
                ldsm4(aL[f], sb + (uint32_t)((AL_OFF + aoff[f] + ks * 16) * 2));
            }
            #pragma unroll
            for (int n2 = 0; n2 < 2; ++n2) {
                uint32_t bH[4], bL[4];
                ldsm4(bH, sb + (uint32_t)((BH_OFF + boff[n2] + ks * 16) * 2));
                ldsm4(bL, sb + (uint32_t)((BL_OFF + boff[n2] + ks * 16) * 2));
                #pragma unroll
                for (int f = 0; f < 2; ++f) {
                    mma16(acc[f][n2 * 2 + 0], aH[f], bH[0], bH[1]);
                    mma16(acc[f][n2 * 2 + 1], aH[f], bH[2], bH[3]);
                    mma16(acc[f][n2 * 2 + 0], aL[f], bH[0], bH[1]);
                    mma16(acc[f][n2 * 2 + 1], aL[f], bH[2], bH[3]);
                    mma16(acc[f][n2 * 2 + 0], aH[f], bL[0], bL[1]);
                    mma16(acc[f][n2 * 2 + 1], aH[f], bL[2], bL[3]);
                }
            }
        }
        __syncthreads();
    }

    // write partials
    float* op = g_part + (size_t)split * (B_ * E_ * T_);
    #pragma unroll
    for (int f = 0; f < 2; ++f) {
        int r0 = mrow0 + mi * 32 + f * 16 + (lane >> 2);
        #pragma unroll
        for (int nt = 0; nt < 4; ++nt) {
            int c = ni * 32 + nt * 8 + (lane & 3) * 2;
            float2 v0 = make_float2(acc[f][nt][0], acc[f][nt][1]);
            float2 v1 = make_float2(acc[f][nt][2], acc[f][nt][3]);
            *(float2*)(op + (size_t)r0 * T_ + c)       = v0;
            *(float2*)(op + (size_t)(r0 + 8) * T_ + c) = v1;
        }
    }

    // semaphore: last CTA of this m-tile reduces partials + bias -> out
    __threadfence();
    __syncthreads();
    if (tid == 0) {
        unsigned int old = atomicAdd(&g_sem[mblk], 1u);
        s_last = (old == KSPLIT - 1) ? 1u : 0u;
    }
    __syncthreads();
    if (s_last) {
        // 64 rows x 32 float4 cols = 2048 float4; 8 per thread
        #pragma unroll
        for (int i2 = 0; i2 < 8; ++i2) {
            int i   = i2 * 256 + tid;
            int row = i >> 5;              // 0..63
            int c4  = i & 31;              // float4 col
            size_t off = (size_t)(mrow0 + row) * T_ + c4 * 4;
            float4 s = ((const float4*)bias)[c4];
            #pragma unroll
            for (int sp = 0; sp < KSPLIT; ++sp) {
                float4 v = *(const float4*)(g_part + (size_t)sp * (B_ * E_ * T_) + off);
                s.x += v.x; s.y += v.y; s.z += v.z; s.w += v.w;
            }
            *(float4*)(out + off) = s;
        }
        if (tid == 0) g_sem[mblk] = 0;     // self-reset for next replay
    }
}

// ---------------------------------------------------------------------------
extern "C" void kernel_launch(void* const* d_in, const int* in_sizes, int n_in,
                              void* d_out, int out_size)
{
    const float* hs     = (const float*)d_in[0];
    const int*   idx    = (const int*)  d_in[1];
    const int*   counts = (const int*)  d_in[2];
    const int*   nent   = (const int*)  d_in[3];
    const float* fcw    = (const float*)d_in[4];
    const float* fcb    = (const float*)d_in[5];
    float*       out    = (float*)d_out;

    const int smem_bytes = 2 * STG_ELE * 2;   // 61440
    cudaFuncSetAttribute(mma_gemm, cudaFuncAttributeMaxDynamicSharedMemorySize,
                         smem_bytes);

    pool_kernel<<<B_ * E_, 256>>>(hs, idx, counts, nent, fcw);
    mma_gemm<<<dim3(B_ * E_ / 64, KSPLIT), 256, smem_bytes>>>(fcb, out);
}

// round 16
// speedup vs baseline: 1.0789x; 1.0789x over previous
#include <cuda_runtime.h>
#include <cuda_bf16.h>
#include <cstdint>

#define B_ 32
#define S_ 2048
#define D_ 1024
#define E_ 64
#define K_ 8
#define T_ 128       // N_TAGS
#define KSPLIT 8
#define KCHUNK 128   // K per split
#define KS 32        // k sub-chunk (bf16 elems) staged in smem
#define RSTR 40      // bf16 elems per smem row (80B: conflict-free, 16B aligned)
#define AH_OFF 0
#define AL_OFF (64 * RSTR)          // 2560
#define BH_OFF (2 * 64 * RSTR)      // 5120
#define BL_OFF (BH_OFF + 128 * RSTR) // 10240
#define STG_ELE (BL_OFF + 128 * RSTR) // 15360 bf16 = 30720 B per stage

// Scratch (allocation-free rule: __device__ globals)
__device__ __nv_bfloat16 g_eh[B_ * E_ * D_];     // 4 MB pooled, bf16-hi
__device__ __nv_bfloat16 g_el[B_ * E_ * D_];     // 4 MB pooled, bf16-lo
__device__ __nv_bfloat16 g_wh[T_ * D_];          // fc_w bf16-hi [T][D]
__device__ __nv_bfloat16 g_wl[T_ * D_];          // fc_w bf16-lo [T][D]

// ---- helpers ----------------------------------------------------------------
__device__ __forceinline__ uint32_t pack_hi_lo(float a, float b,
                                               float& ra, float& rb) {
    __nv_bfloat16 ha = __float2bfloat16_rn(a);
    __nv_bfloat16 hb = __float2bfloat16_rn(b);
    ra = a - __bfloat162float(ha);
    rb = b - __bfloat162float(hb);
    uint16_t ua = *(uint16_t*)&ha, ub = *(uint16_t*)&hb;
    return (uint32_t)ua | ((uint32_t)ub << 16);
}
__device__ __forceinline__ uint32_t pack_bf2(float a, float b) {
    __nv_bfloat16 ha = __float2bfloat16_rn(a);
    __nv_bfloat16 hb = __float2bfloat16_rn(b);
    uint16_t ua = *(uint16_t*)&ha, ub = *(uint16_t*)&hb;
    return (uint32_t)ua | ((uint32_t)ub << 16);
}

__device__ __forceinline__ void ldsm4(uint32_t* r, uint32_t addr) {
    asm volatile("ldmatrix.sync.aligned.m8n8.x4.shared.b16 {%0,%1,%2,%3}, [%4];"
                 : "=r"(r[0]), "=r"(r[1]), "=r"(r[2]), "=r"(r[3]) : "r"(addr));
}
__device__ __forceinline__ void mma16(float* d, const uint32_t* a,
                                      uint32_t b0, uint32_t b1) {
    asm volatile(
        "mma.sync.aligned.m16n8k16.row.col.f32.bf16.bf16.f32 "
        "{%0,%1,%2,%3}, {%4,%5,%6,%7}, {%8,%9}, {%0,%1,%2,%3};"
        : "+f"(d[0]), "+f"(d[1]), "+f"(d[2]), "+f"(d[3])
        : "r"(a[0]), "r"(a[1]), "r"(a[2]), "r"(a[3]), "r"(b0), "r"(b1));
}
__device__ __forceinline__ void cp16(uint32_t dst, const void* src) {
    asm volatile("cp.async.cg.shared.global [%0], [%1], 16;"
                 :: "r"(dst), "l"(src) : "memory");
}
__device__ __forceinline__ void red2(float* p, float x, float y) {
    asm volatile("red.global.add.v2.f32 [%0], {%1, %2};"
                 :: "l"(p), "f"(x), "f"(y) : "memory");
}

// ---------------------------------------------------------------------------
// Kernel P: gather + masked mean pool -> bf16 hi/lo split outputs (R12-proven).
// Blocks < 512 also split fc_w; blocks < 1024 also init out = bias (for the
// GEMM's atomic accumulation).
// ---------------------------------------------------------------------------
__global__ __launch_bounds__(256) void pool_kernel(
    const float* __restrict__ hs,      // [B,S,D]
    const int*   __restrict__ idx,     // [B,E,K]
    const int*   __restrict__ counts,  // [B,E]
    const int*   __restrict__ nent,    // [B]
    const float* __restrict__ W,       // fc_w [T,D]
    const float* __restrict__ bias,    // [T]
    float*       __restrict__ out)     // [B*E, T]
{
    int be = blockIdx.x;           // 0..2047
    int b  = be >> 6;
    int e  = be & 63;
    int t  = threadIdx.x;

    int cnt    = counts[be];
    int ne     = nent[b];
    int4 ia    = *(const int4*)(idx + be * K_);
    int4 ib    = *(const int4*)(idx + be * K_ + 4);
    bool active = (e < ne);

    int r[8] = {ia.x, ia.y, ia.z, ia.w, ib.x, ib.y, ib.z, ib.w};
    #pragma unroll
    for (int k = 1; k < K_; ++k)
        r[k] = (k < cnt) ? r[k] : r[0];   // clamp -> dup loads hit L1

    float4 acc = make_float4(0.f, 0.f, 0.f, 0.f);
    if (active) {
        const float* base = hs + (size_t)b * (S_ * D_) + t * 4;
        float4 v[8];
        #pragma unroll
        for (int k = 0; k < K_; ++k)      // 8 unconditional batched LDG.128
            v[k] = *(const float4*)(base + (size_t)r[k] * D_);
        float inv = 1.0f / (float)cnt;
        #pragma unroll
        for (int k = 0; k < K_; ++k) {
            float w = (k < cnt) ? inv : 0.f;
            acc.x = fmaf(v[k].x, w, acc.x);
            acc.y = fmaf(v[k].y, w, acc.y);
            acc.z = fmaf(v[k].z, w, acc.z);
            acc.w = fmaf(v[k].w, w, acc.w);
        }
    }

    float rx, ry, rz, rw;
    uint2 hv, lv;
    hv.x = pack_hi_lo(acc.x, acc.y, rx, ry);
    hv.y = pack_hi_lo(acc.z, acc.w, rz, rw);
    lv.x = pack_bf2(rx, ry);
    lv.y = pack_bf2(rz, rw);
    *(uint2*)(g_eh + (size_t)be * D_ + t * 4) = hv;
    *(uint2*)(g_el + (size_t)be * D_ + t * 4) = lv;

    // fc_w hi/lo split: 512 blocks x 256 elements
    if (blockIdx.x < (T_ * D_) / 256) {
        int i = blockIdx.x * 256 + t;
        float w = W[i];
        __nv_bfloat16 wh = __float2bfloat16_rn(w);
        g_wh[i] = wh;
        g_wl[i] = __float2bfloat16_rn(w - __bfloat162float(wh));
    }
    // out = bias init: 1024 blocks x 256 floats
    if (blockIdx.x < (B_ * E_ * T_) / 256) {
        int i = blockIdx.x * 256 + t;
        out[i] = bias[i & (T_ - 1)];
    }
}

// ---------------------------------------------------------------------------
// Kernel B: bf16x3 split-K GEMM (R12-proven mainloop); epilogue accumulates
// straight into out via red.global.add.v2.f32 (out pre-initialized to bias).
// grid = (32 m-tiles, 8 k-splits) = 256 CTAs (2/SM), 256 threads (8 warps).
// ---------------------------------------------------------------------------
__global__ __launch_bounds__(256, 2) void mma_gemm(float* __restrict__ out)
{
    extern __shared__ __nv_bfloat16 sm[];
    uint32_t smb;
    asm("{ .reg .u64 t; cvta.to.shared.u64 t, %1; cvt.u32.u64 %0, t; }"
        : "=r"(smb) : "l"(sm));

    int tid  = threadIdx.x;
    int lane = tid & 31;
    int warp = tid >> 5;
    int mi = warp >> 2;            // 0..1  -> m-sub (32 rows)
    int ni = warp & 3;             // 0..3  -> n-sub (32 cols)
    int mrow0 = blockIdx.x * 64;
    int split = blockIdx.y;
    int kbase = split * KCHUNK;

    // ldmatrix per-lane offsets (bf16 elems)
    int tile = lane >> 3;
    int tr   = lane & 7;
    int aoff[2], boff[2];
    #pragma unroll
    for (int f = 0; f < 2; ++f)
        aoff[f] = (mi * 32 + f * 16 + (tile & 1) * 8 + tr) * RSTR + (tile >> 1) * 8;
    #pragma unroll
    for (int n2 = 0; n2 < 2; ++n2)
        boff[n2] = (ni * 32 + n2 * 16 + (tile >> 1) * 8 + tr) * RSTR + (tile & 1) * 8;

    float acc[2][4][4];
    #pragma unroll
    for (int f = 0; f < 2; ++f)
        #pragma unroll
        for (int n = 0; n < 4; ++n)
            #pragma unroll
            for (int p = 0; p < 4; ++p) acc[f][n][p] = 0.f;

    auto issue = [&](int stg, int it) {
        int kc = kbase + it * KS;
        uint32_t sb = smb + (uint32_t)(stg * STG_ELE * 2);
        {
            int row = tid >> 2, q = tid & 3;
            size_t g = (size_t)(mrow0 + row) * D_ + kc + q * 8;
            cp16(sb + (uint32_t)((AH_OFF + row * RSTR + q * 8) * 2), g_eh + g);
            cp16(sb + (uint32_t)((AL_OFF + row * RSTR + q * 8) * 2), g_el + g);
        }
        #pragma unroll
        for (int j = 0; j < 2; ++j) {
            int i   = tid + j * 256;
            int row = i >> 2, q = i & 3;
            size_t g = (size_t)row * D_ + kc + q * 8;
            cp16(sb + (uint32_t)((BH_OFF + row * RSTR + q * 8) * 2), g_wh + g);
            cp16(sb + (uint32_t)((BL_OFF + row * RSTR + q * 8) * 2), g_wl + g);
        }
        asm volatile("cp.async.commit_group;" ::: "memory");
    };

    issue(0, 0);

    #pragma unroll 1
    for (int it = 0; it < KCHUNK / KS; ++it) {
        int s = it & 1;
        asm volatile("cp.async.wait_group 0;" ::: "memory");
        __syncthreads();
        if (it + 1 < KCHUNK / KS) issue((it + 1) & 1, it + 1);

        uint32_t sb = smb + (uint32_t)(s * STG_ELE * 2);

        #pragma unroll
        for (int ks = 0; ks < KS / 16; ++ks) {
            uint32_t aH[2][4], aL[2][4];
            #pragma unroll
            for (int f = 0; f < 2; ++f) {
                ldsm4(aH[f], sb + (uint32_t)((AH_OFF + aoff[f] + ks * 16) * 2));
                ldsm4(aL[f], sb + (uint32_t)((AL_OFF + aoff[f] + ks * 16) * 2));
            }
            #pragma unroll
            for (int n2 = 0; n2 < 2; ++n2) {
                uint32_t bH[4], bL[4];
                ldsm4(bH, sb + (uint32_t)((BH_OFF + boff[n2] + ks * 16) * 2));
                ldsm4(bL, sb + (uint32_t)((BL_OFF + boff[n2] + ks * 16) * 2));
                #pragma unroll
                for (int f = 0; f < 2; ++f) {
                    mma16(acc[f][n2 * 2 + 0], aH[f], bH[0], bH[1]);
                    mma16(acc[f][n2 * 2 + 1], aH[f], bH[2], bH[3]);
                    mma16(acc[f][n2 * 2 + 0], aL[f], bH[0], bH[1]);
                    mma16(acc[f][n2 * 2 + 1], aL[f], bH[2], bH[3]);
                    mma16(acc[f][n2 * 2 + 0], aH[f], bL[0], bL[1]);
                    mma16(acc[f][n2 * 2 + 1], aH[f], bL[2], bL[3]);
                }
            }
        }
        __syncthreads();
    }

    // epilogue: atomically accumulate into out (pre-initialized to bias)
    #pragma unroll
    for (int f = 0; f < 2; ++f) {
        int r0 = mrow0 + mi * 32 + f * 16 + (lane >> 2);
        #pragma unroll
        for (int nt = 0; nt < 4; ++nt) {
            int c = ni * 32 + nt * 8 + (lane & 3) * 2;
            red2(out + (size_t)r0 * T_ + c,       acc[f][nt][0], acc[f][nt][1]);
            red2(out + (size_t)(r0 + 8) * T_ + c, acc[f][nt][2], acc[f][nt][3]);
        }
    }
}

// ---------------------------------------------------------------------------
extern "C" void kernel_launch(void* const* d_in, const int* in_sizes, int n_in,
                              void* d_out, int out_size)
{
    const float* hs     = (const float*)d_in[0];
    const int*   idx    = (const int*)  d_in[1];
    const int*   counts = (const int*)  d_in[2];
    const int*   nent   = (const int*)  d_in[3];
    const float* fcw    = (const float*)d_in[4];
    const float* fcb    = (const float*)d_in[5];
    float*       out    = (float*)d_out;

    const int smem_bytes = 2 * STG_ELE * 2;   // 61440
    cudaFuncSetAttribute(mma_gemm, cudaFuncAttributeMaxDynamicSharedMemorySize,
                         smem_bytes);

    pool_kernel<<<B_ * E_, 256>>>(hs, idx, counts, nent, fcw, fcb, out);
    mma_gemm<<<dim3(B_ * E_ / 64, KSPLIT), 256, smem_bytes>>>(out);
}

// round 17
// speedup vs baseline: 1.2448x; 1.1537x over previous
#include <cuda_runtime.h>
#include <cuda_bf16.h>
#include <cstdint>

#define B_ 32
#define S_ 2048
#define D_ 1024
#define E_ 64
#define K_ 8
#define T_ 128       // N_TAGS
#define KSPLIT 8
#define KCHUNK 128   // K per split
#define KS 32        // k sub-chunk (bf16 elems) staged in smem
#define RSTR 40      // bf16 elems per smem row (80B: conflict-free, 16B aligned)
#define AH_OFF 0
#define AL_OFF (64 * RSTR)          // 2560
#define BH_OFF (2 * 64 * RSTR)      // 5120
#define BL_OFF (BH_OFF + 128 * RSTR) // 10240
#define STG_ELE (BL_OFF + 128 * RSTR) // 15360 bf16 = 30720 B per stage
#define NSTG 3

// Scratch (allocation-free rule: __device__ globals)
__device__ __nv_bfloat16 g_eh[B_ * E_ * D_];     // 4 MB pooled, bf16-hi
__device__ __nv_bfloat16 g_el[B_ * E_ * D_];     // 4 MB pooled, bf16-lo
__device__ __nv_bfloat16 g_wh[T_ * D_];          // fc_w bf16-hi [T][D]
__device__ __nv_bfloat16 g_wl[T_ * D_];          // fc_w bf16-lo [T][D]

// ---- helpers ----------------------------------------------------------------
__device__ __forceinline__ uint32_t pack_hi_lo(float a, float b,
                                               float& ra, float& rb) {
    __nv_bfloat16 ha = __float2bfloat16_rn(a);
    __nv_bfloat16 hb = __float2bfloat16_rn(b);
    ra = a - __bfloat162float(ha);
    rb = b - __bfloat162float(hb);
    uint16_t ua = *(uint16_t*)&ha, ub = *(uint16_t*)&hb;
    return (uint32_t)ua | ((uint32_t)ub << 16);
}
__device__ __forceinline__ uint32_t pack_bf2(float a, float b) {
    __nv_bfloat16 ha = __float2bfloat16_rn(a);
    __nv_bfloat16 hb = __float2bfloat16_rn(b);
    uint16_t ua = *(uint16_t*)&ha, ub = *(uint16_t*)&hb;
    return (uint32_t)ua | ((uint32_t)ub << 16);
}

__device__ __forceinline__ void ldsm4(uint32_t* r, uint32_t addr) {
    asm volatile("ldmatrix.sync.aligned.m8n8.x4.shared.b16 {%0,%1,%2,%3}, [%4];"
                 : "=r"(r[0]), "=r"(r[1]), "=r"(r[2]), "=r"(r[3]) : "r"(addr));
}
__device__ __forceinline__ void mma16(float* d, const uint32_t* a,
                                      uint32_t b0, uint32_t b1) {
    asm volatile(
        "mma.sync.aligned.m16n8k16.row.col.f32.bf16.bf16.f32 "
        "{%0,%1,%2,%3}, {%4,%5,%6,%7}, {%8,%9}, {%0,%1,%2,%3};"
        : "+f"(d[0]), "+f"(d[1]), "+f"(d[2]), "+f"(d[3])
        : "r"(a[0]), "r"(a[1]), "r"(a[2]), "r"(a[3]), "r"(b0), "r"(b1));
}
__device__ __forceinline__ void cp16(uint32_t dst, const void* src) {
    asm volatile("cp.async.cg.shared.global [%0], [%1], 16;"
                 :: "r"(dst), "l"(src) : "memory");
}
__device__ __forceinline__ void red2(float* p, float x, float y) {
    asm volatile("red.global.add.v2.f32 [%0], {%1, %2};"
                 :: "l"(p), "f"(x), "f"(y) : "memory");
}

// ---------------------------------------------------------------------------
// Kernel P: gather + masked mean pool -> bf16 hi/lo split outputs (R12-proven).
// Blocks < 512 also split fc_w; blocks < 1024 also init out = bias.
// ---------------------------------------------------------------------------
__global__ __launch_bounds__(256) void pool_kernel(
    const float* __restrict__ hs,      // [B,S,D]
    const int*   __restrict__ idx,     // [B,E,K]
    const int*   __restrict__ counts,  // [B,E]
    const int*   __restrict__ nent,    // [B]
    const float* __restrict__ W,       // fc_w [T,D]
    const float* __restrict__ bias,    // [T]
    float*       __restrict__ out)     // [B*E, T]
{
    int be = blockIdx.x;           // 0..2047
    int b  = be >> 6;
    int e  = be & 63;
    int t  = threadIdx.x;

    int cnt    = counts[be];
    int ne     = nent[b];
    int4 ia    = *(const int4*)(idx + be * K_);
    int4 ib    = *(const int4*)(idx + be * K_ + 4);
    bool active = (e < ne);

    int r[8] = {ia.x, ia.y, ia.z, ia.w, ib.x, ib.y, ib.z, ib.w};
    #pragma unroll
    for (int k = 1; k < K_; ++k)
        r[k] = (k < cnt) ? r[k] : r[0];   // clamp -> dup loads hit L1

    float4 acc = make_float4(0.f, 0.f, 0.f, 0.f);
    if (active) {
        const float* base = hs + (size_t)b * (S_ * D_) + t * 4;
        float4 v[8];
        #pragma unroll
        for (int k = 0; k < K_; ++k)      // 8 unconditional batched LDG.128
            v[k] = *(const float4*)(base + (size_t)r[k] * D_);
        float inv = 1.0f / (float)cnt;
        #pragma unroll
        for (int k = 0; k < K_; ++k) {
            float w = (k < cnt) ? inv : 0.f;
            acc.x = fmaf(v[k].x, w, acc.x);
            acc.y = fmaf(v[k].y, w, acc.y);
            acc.z = fmaf(v[k].z, w, acc.z);
            acc.w = fmaf(v[k].w, w, acc.w);
        }
    }

    float rx, ry, rz, rw;
    uint2 hv, lv;
    hv.x = pack_hi_lo(acc.x, acc.y, rx, ry);
    hv.y = pack_hi_lo(acc.z, acc.w, rz, rw);
    lv.x = pack_bf2(rx, ry);
    lv.y = pack_bf2(rz, rw);
    *(uint2*)(g_eh + (size_t)be * D_ + t * 4) = hv;
    *(uint2*)(g_el + (size_t)be * D_ + t * 4) = lv;

    // fc_w hi/lo split: 512 blocks x 256 elements
    if (blockIdx.x < (T_ * D_) / 256) {
        int i = blockIdx.x * 256 + t;
        float w = W[i];
        __nv_bfloat16 wh = __float2bfloat16_rn(w);
        g_wh[i] = wh;
        g_wl[i] = __float2bfloat16_rn(w - __bfloat162float(wh));
    }
    // out = bias init: 1024 blocks x 256 floats
    if (blockIdx.x < (B_ * E_ * T_) / 256) {
        int i = blockIdx.x * 256 + t;
        out[i] = bias[i & (T_ - 1)];
    }
}

// ---------------------------------------------------------------------------
// Kernel B: bf16x3 split-K GEMM, 3-stage cp.async pipeline (chunks 1-3 load
// under chunks 0-2 compute). Epilogue accumulates into out via red.v2.f32.
// grid = (32 m-tiles, 8 k-splits) = 256 CTAs (2/SM), 256 threads (8 warps).
// ---------------------------------------------------------------------------
__global__ __launch_bounds__(256, 2) void mma_gemm(float* __restrict__ out)
{
    extern __shared__ __nv_bfloat16 sm[];
    uint32_t smb;
    asm("{ .reg .u64 t; cvta.to.shared.u64 t, %1; cvt.u32.u64 %0, t; }"
        : "=r"(smb) : "l"(sm));

    int tid  = threadIdx.x;
    int lane = tid & 31;
    int warp = tid >> 5;
    int mi = warp >> 2;            // 0..1  -> m-sub (32 rows)
    int ni = warp & 3;             // 0..3  -> n-sub (32 cols)
    int mrow0 = blockIdx.x * 64;
    int split = blockIdx.y;
    int kbase = split * KCHUNK;

    // ldmatrix per-lane offsets (bf16 elems)
    int tile = lane >> 3;
    int tr   = lane & 7;
    int aoff[2], boff[2];
    #pragma unroll
    for (int f = 0; f < 2; ++f)
        aoff[f] = (mi * 32 + f * 16 + (tile & 1) * 8 + tr) * RSTR + (tile >> 1) * 8;
    #pragma unroll
    for (int n2 = 0; n2 < 2; ++n2)
        boff[n2] = (ni * 32 + n2 * 16 + (tile >> 1) * 8 + tr) * RSTR + (tile & 1) * 8;

    float acc[2][4][4];
    #pragma unroll
    for (int f = 0; f < 2; ++f)
        #pragma unroll
        for (int n = 0; n < 4; ++n)
            #pragma unroll
            for (int p = 0; p < 4; ++p) acc[f][n][p] = 0.f;

    auto issue = [&](int stg, int it) {
        int kc = kbase + it * KS;
        uint32_t sb = smb + (uint32_t)(stg * STG_ELE * 2);
        {
            int row = tid >> 2, q = tid & 3;
            size_t g = (size_t)(mrow0 + row) * D_ + kc + q * 8;
            cp16(sb + (uint32_t)((AH_OFF + row * RSTR + q * 8) * 2), g_eh + g);
            cp16(sb + (uint32_t)((AL_OFF + row * RSTR + q * 8) * 2), g_el + g);
        }
        #pragma unroll
        for (int j = 0; j < 2; ++j) {
            int i   = tid + j * 256;
            int row = i >> 2, q = i & 3;
            size_t g = (size_t)row * D_ + kc + q * 8;
            cp16(sb + (uint32_t)((BH_OFF + row * RSTR + q * 8) * 2), g_wh + g);
            cp16(sb + (uint32_t)((BL_OFF + row * RSTR + q * 8) * 2), g_wl + g);
        }
        asm volatile("cp.async.commit_group;" ::: "memory");
    };

    auto compute = [&](int stg) {
        uint32_t sb = smb + (uint32_t)(stg * STG_ELE * 2);
        #pragma unroll
        for (int ks = 0; ks < KS / 16; ++ks) {
            uint32_t aH[2][4], aL[2][4];
            #pragma unroll
            for (int f = 0; f < 2; ++f) {
                ldsm4(aH[f], sb + (uint32_t)((AH_OFF + aoff[f] + ks * 16) * 2));
                ldsm4(aL[f], sb + (uint32_t)((AL_OFF + aoff[f] + ks * 16) * 2));
            }
            #pragma unroll
            for (int n2 = 0; n2 < 2; ++n2) {
                uint32_t bH[4], bL[4];
                ldsm4(bH, sb + (uint32_t)((BH_OFF + boff[n2] + ks * 16) * 2));
                ldsm4(bL, sb + (uint32_t)((BL_OFF + boff[n2] + ks * 16) * 2));
                #pragma unroll
                for (int f = 0; f < 2; ++f) {
                    mma16(acc[f][n2 * 2 + 0], aH[f], bH[0], bH[1]);
                    mma16(acc[f][n2 * 2 + 1], aH[f], bH[2], bH[3]);
                    mma16(acc[f][n2 * 2 + 0], aL[f], bH[0], bH[1]);
                    mma16(acc[f][n2 * 2 + 1], aL[f], bH[2], bH[3]);
                    mma16(acc[f][n2 * 2 + 0], aH[f], bL[0], bL[1]);
                    mma16(acc[f][n2 * 2 + 1], aH[f], bL[2], bL[3]);
                }
            }
        }
    };

    // 3-stage pipeline over the 4 k-chunks
    issue(0, 0);
    issue(1, 1);
    issue(2, 2);
    asm volatile("cp.async.wait_group 2;" ::: "memory");   // chunk 0 ready
    __syncthreads();
    compute(0);
    __syncthreads();                                       // buf0 free (WAR)
    issue(0, 3);
    asm volatile("cp.async.wait_group 2;" ::: "memory");   // chunk 1 ready
    __syncthreads();
    compute(1);
    asm volatile("cp.async.wait_group 1;" ::: "memory");   // chunk 2 ready
    __syncthreads();
    compute(2);
    asm volatile("cp.async.wait_group 0;" ::: "memory");   // chunk 3 ready
    __syncthreads();
    compute(0);

    // epilogue: atomically accumulate into out (pre-initialized to bias)
    #pragma unroll
    for (int f = 0; f < 2; ++f) {
        int r0 = mrow0 + mi * 32 + f * 16 + (lane >> 2);
        #pragma unroll
        for (int nt = 0; nt < 4; ++nt) {
            int c = ni * 32 + nt * 8 + (lane & 3) * 2;
            red2(out + (size_t)r0 * T_ + c,       acc[f][nt][0], acc[f][nt][1]);
            red2(out + (size_t)(r0 + 8) * T_ + c, acc[f][nt][2], acc[f][nt][3]);
        }
    }
}

// ---------------------------------------------------------------------------
extern "C" void kernel_launch(void* const* d_in, const int* in_sizes, int n_in,
                              void* d_out, int out_size)
{
    const float* hs     = (const float*)d_in[0];
    const int*   idx    = (const int*)  d_in[1];
    const int*   counts = (const int*)  d_in[2];
    const int*   nent   = (const int*)  d_in[3];
    const float* fcw    = (const float*)d_in[4];
    const float* fcb    = (const float*)d_in[5];
    float*       out    = (float*)d_out;

    const int smem_bytes = NSTG * STG_ELE * 2;   // 92160
    cudaFuncSetAttribute(mma_gemm, cudaFuncAttributeMaxDynamicSharedMemorySize,
                         smem_bytes);

    pool_kernel<<<B_ * E_, 256>>>(hs, idx, counts, nent, fcw, fcb, out);
    mma_gemm<<<dim3(B_ * E_ / 64, KSPLIT), 256, smem_bytes>>>(out);
}